// round 14
// baseline (speedup 1.0000x reference)
#include <cuda_runtime.h>
#include <cuda_bf16.h>
#include <cstdint>

#define BATCH 16
#define SQ    1024
#define SKV   1024
#define HD    256

#define QT 32              // q-rows per block
#define KT 64              // k-tile width per iteration
#define NKT (SKV / KT)     // 16
#define LDA 264            // padded bf16 leading dim
#define BUFB (64 * LDA)    // bf16 elements per K buffer

// ---- static device scratch ----
__device__ __nv_bfloat16 g_qb[BATCH * SQ * HD];
__device__ __nv_bfloat16 g_kb[BATCH * SKV * HD];
__device__ float g_rowsum[BATCH * SQ];
__device__ float g_cpart[BATCH * 32 * SKV];    // per-32-row-chunk column partials
__device__ float g_csum[BATCH * SKV];          // reduced column sums
__device__ float g_outpart[BATCH * 64 * HD];   // per-kchunk GEMV partials

__device__ __forceinline__ void cp16(void* dst, const void* src) {
    unsigned int d = (unsigned int)__cvta_generic_to_shared(dst);
    asm volatile("cp.async.cg.shared.global [%0], [%1], 16;\n" :: "r"(d), "l"(src));
}

__device__ __forceinline__ void mma16816(float c[4], const unsigned a[4],
                                         unsigned b0, unsigned b1) {
    asm volatile(
        "mma.sync.aligned.m16n8k16.row.col.f32.bf16.bf16.f32 "
        "{%0,%1,%2,%3}, {%4,%5,%6,%7}, {%8,%9}, {%0,%1,%2,%3};"
        : "+f"(c[0]), "+f"(c[1]), "+f"(c[2]), "+f"(c[3])
        : "r"(a[0]), "r"(a[1]), "r"(a[2]), "r"(a[3]), "r"(b0), "r"(b1));
}

__device__ __forceinline__ void ldsm4(unsigned& r0, unsigned& r1,
                                      unsigned& r2, unsigned& r3, unsigned addr) {
    asm volatile("ldmatrix.sync.aligned.m8n8.x4.shared.b16 {%0,%1,%2,%3}, [%4];"
                 : "=r"(r0), "=r"(r1), "=r"(r2), "=r"(r3) : "r"(addr));
}

// ---------------------------------------------------------------------------
// K0: convert Q and K to bf16
// ---------------------------------------------------------------------------
__global__ void k_convert(const float* __restrict__ q, const float* __restrict__ k) {
    int i = (blockIdx.x * blockDim.x + threadIdx.x) * 4;
    float4 qv = *(const float4*)(q + i);
    float4 kv = *(const float4*)(k + i);
    __nv_bfloat162* qo = (__nv_bfloat162*)(g_qb + i);
    __nv_bfloat162* ko = (__nv_bfloat162*)(g_kb + i);
    qo[0] = __floats2bfloat162_rn(qv.x, qv.y);
    qo[1] = __floats2bfloat162_rn(qv.z, qv.w);
    ko[0] = __floats2bfloat162_rn(kv.x, kv.y);
    ko[1] = __floats2bfloat162_rn(kv.z, kv.w);
}

// ---------------------------------------------------------------------------
// K1: scores. 32 q-rows x 1024 k per block. m16n8k16 mma, 3-buffer cp.async
//     pipeline (ONE __syncthreads per tile), ldmatrix.x4 B-fragments,
//     mask+exp in registers, direct p stores, deterministic rowsum.
// ---------------------------------------------------------------------------
__global__ void __launch_bounds__(256, 2) k_scores(const int* __restrict__ mask,
                                                   float* __restrict__ p_out) {
    extern __shared__ char smraw[];
    __nv_bfloat16* Kb = (__nv_bfloat16*)smraw;         // 3 buffers of 64 x LDA
    float* rowp = (float*)(Kb + 3 * BUFB);             // 32 x 4

    const int b    = blockIdx.y;
    const int q0   = blockIdx.x * QT;
    const int tid  = threadIdx.x;
    const int lane = tid & 31;
    const int warp = tid >> 5;
    const int wy   = warp >> 2;     // 0..1 : 16-row band
    const int wx   = warp & 3;      // 0..3 : 16-col band
    const int g    = lane >> 2;     // 0..7
    const int t    = lane & 3;      // 0..3

    const __nv_bfloat16* Kg = g_kb + (size_t)b * SKV * HD;

    // stage: Q -> buf2, K0 -> buf0 (group0), K1 -> buf1 (group1)
    {
        const __nv_bfloat16* Qg = g_qb + (size_t)(b * SQ + q0) * HD;
        #pragma unroll
        for (int j = 0; j < 4; j++) {
            int s = tid + j * 256; int r = s >> 5, c8 = s & 31;
            cp16(Kb + 2 * BUFB + r * LDA + c8 * 8, Qg + r * HD + c8 * 8);
        }
        #pragma unroll
        for (int j = 0; j < 8; j++) {
            int s = tid + j * 256; int r = s >> 5, c8 = s & 31;
            cp16(Kb + r * LDA + c8 * 8, Kg + r * HD + c8 * 8);
        }
        asm volatile("cp.async.commit_group;\n");
        #pragma unroll
        for (int j = 0; j < 8; j++) {
            int s = tid + j * 256; int r = s >> 5, c8 = s & 31;
            cp16(Kb + BUFB + r * LDA + c8 * 8, Kg + (size_t)(KT + r) * HD + c8 * 8);
        }
        asm volatile("cp.async.commit_group;\n");
        asm volatile("cp.async.wait_group 1;\n");   // Q + K0 done
        __syncthreads();
    }

    // hoist A fragments (all 16 dk steps) from staged Q (buf2)
    unsigned a[16][4];
    {
        const __nv_bfloat16* Qw = Kb + 2 * BUFB + (wy * 16 + g) * LDA;
        #pragma unroll
        for (int dk = 0; dk < 16; dk++) {
            int base = dk * 16 + 2 * t;
            a[dk][0] = *(const unsigned*)(Qw + base);
            a[dk][1] = *(const unsigned*)(Qw + 8 * LDA + base);
            a[dk][2] = *(const unsigned*)(Qw + base + 8);
            a[dk][3] = *(const unsigned*)(Qw + 8 * LDA + base + 8);
        }
    }
    // NOTE: buf2 is first overwritten by the K2 prefetch issued AFTER iter 0's
    // __syncthreads(), which all warps reach only after finishing this hoist.

    float rs0 = 0.0f, rs1 = 0.0f;
    const size_t prow0 = (size_t)(b * SQ + q0 + wy * 16 + g) * SKV;

    // ldmatrix lane address components (within a tile buffer)
    const int n_loc  = wx * 16 + ((lane >> 4) & 1) * 8 + (lane & 7);
    const int k_half = ((lane >> 3) & 1) * 8;

    for (int kt = 0; kt < NKT; kt++) {
        const __nv_bfloat16* cur = Kb + (kt % 3) * BUFB;

        // mask prefetch (LDGs in flight across the wait)
        const int* mrow = mask + prow0 + kt * KT + wx * 16 + 2 * t;
        int2 m00 = *(const int2*)(mrow);
        int2 m01 = *(const int2*)(mrow + 8);
        int2 m10 = *(const int2*)(mrow + (size_t)8 * SKV);
        int2 m11 = *(const int2*)(mrow + (size_t)8 * SKV + 8);

        if (kt + 1 < NKT) asm volatile("cp.async.wait_group 1;\n");
        else              asm volatile("cp.async.wait_group 0;\n");
        __syncthreads();   // tile kt visible; mma(kt-1) reads complete everywhere

        // prefetch tile kt+2 into buf[(kt+2)%3] (safe: see sync above)
        if (kt + 2 < NKT) {
            const __nv_bfloat16* Kn = Kg + (size_t)(kt + 2) * KT * HD;
            __nv_bfloat16* nb = Kb + ((kt + 2) % 3) * BUFB;
            #pragma unroll
            for (int j = 0; j < 8; j++) {
                int s = tid + j * 256; int r = s >> 5, c8 = s & 31;
                cp16(nb + r * LDA + c8 * 8, Kn + r * HD + c8 * 8);
            }
            asm volatile("cp.async.commit_group;\n");
        }

        // MMA over 16 dk steps, B-fragments via ldmatrix.x4
        unsigned baddr = (unsigned)__cvta_generic_to_shared(cur + n_loc * LDA + k_half);
        float c[2][4] = {{0.f,0.f,0.f,0.f},{0.f,0.f,0.f,0.f}};
        #pragma unroll
        for (int dk = 0; dk < 16; dk++) {
            unsigned b00, b01, b10, b11;
            ldsm4(b00, b01, b10, b11, baddr + dk * 32);
            mma16816(c[0], a[dk], b00, b01);
            mma16816(c[1], a[dk], b10, b11);
        }

        // elementwise in registers + rowsum partials + direct p stores
        float* pw0 = p_out + prow0 + kt * KT + wx * 16 + 2 * t;
        #pragma unroll
        for (int nh = 0; nh < 2; nh++) {
            int2 mg  = nh ? m01 : m00;
            int2 mg8 = nh ? m11 : m10;
            float e0 = mg.x  ? __expf(__expf(c[nh][0]) * 0.0625f) : 0.0f;
            float e1 = mg.y  ? __expf(__expf(c[nh][1]) * 0.0625f) : 0.0f;
            float e2 = mg8.x ? __expf(__expf(c[nh][2]) * 0.0625f) : 0.0f;
            float e3 = mg8.y ? __expf(__expf(c[nh][3]) * 0.0625f) : 0.0f;
            rs0 += e0 + e1;
            rs1 += e2 + e3;
            *(float2*)(pw0 + nh * 8)                   = make_float2(e0, e1);
            *(float2*)(pw0 + nh * 8 + (size_t)8 * SKV) = make_float2(e2, e3);
        }
    }

    // rowsum: quad shuffle (fixed order), then 4-warp combine (fixed order)
    rs0 += __shfl_xor_sync(0xffffffffu, rs0, 1);
    rs0 += __shfl_xor_sync(0xffffffffu, rs0, 2);
    rs1 += __shfl_xor_sync(0xffffffffu, rs1, 1);
    rs1 += __shfl_xor_sync(0xffffffffu, rs1, 2);
    if (t == 0) {
        rowp[(wy * 16 + g) * 4 + wx]     = rs0;
        rowp[(wy * 16 + g + 8) * 4 + wx] = rs1;
    }
    __syncthreads();
    if (tid < QT) {
        float s = rowp[tid * 4 + 0] + rowp[tid * 4 + 1]
                + rowp[tid * 4 + 2] + rowp[tid * 4 + 3];
        g_rowsum[b * SQ + q0 + tid] = s;
    }
}

// ---------------------------------------------------------------------------
// K2: normalize p in place (float4 streaming), column partials per 32-row chunk
// ---------------------------------------------------------------------------
__global__ void __launch_bounds__(256) k_norm(float* __restrict__ p) {
    const int qc = blockIdx.x;      // 0..31 (32 rows each)
    const int b  = blockIdx.y;
    const int k4 = threadIdx.x * 4;

    __shared__ float sinv[32];
    if (threadIdx.x < 32)
        sinv[threadIdx.x] = 1.0f / g_rowsum[b * SQ + qc * 32 + threadIdx.x];
    __syncthreads();

    float* pp = p + ((size_t)b * SQ + qc * 32) * SKV + k4;
    float4 acc = {0.f, 0.f, 0.f, 0.f};
    #pragma unroll 4
    for (int q = 0; q < 32; q++) {
        float4 v = *(float4*)(pp + (size_t)q * SKV);
        float s = sinv[q];
        v.x *= s; v.y *= s; v.z *= s; v.w *= s;
        *(float4*)(pp + (size_t)q * SKV) = v;
        acc.x += v.x; acc.y += v.y; acc.z += v.z; acc.w += v.w;
    }
    *(float4*)&g_cpart[(size_t)(b * 32 + qc) * SKV + k4] = acc;
}

// ---------------------------------------------------------------------------
// K2b: fixed-order reduce of 32 qchunk partials -> g_csum
// ---------------------------------------------------------------------------
__global__ void __launch_bounds__(256) k_csum() {
    int i = blockIdx.x * 256 + threadIdx.x;      // B*SKV = 16384
    int b = i / SKV, k = i % SKV;
    float s = 0.0f;
    #pragma unroll
    for (int y = 0; y < 32; y++) s += g_cpart[(size_t)(b * 32 + y) * SKV + k];
    g_csum[i] = s;
}

// ---------------------------------------------------------------------------
// K3: out_part[b,ch,d] = sum_{k in 16-chunk} csum[b,k] * V[b,k,d]
// ---------------------------------------------------------------------------
__global__ void __launch_bounds__(256) k_gemv(const float* __restrict__ v) {
    const int b  = blockIdx.y;
    const int ch = blockIdx.x;     // 16 k per chunk
    const int t  = threadIdx.x;

    __shared__ float cv[16];
    if (t < 16) cv[t] = g_csum[b * SKV + ch * 16 + t];
    __syncthreads();

    const float* vb = v + ((size_t)b * SKV + ch * 16) * HD + t;
    float acc = 0.0f;
    #pragma unroll
    for (int k = 0; k < 16; k++) acc += cv[k] * vb[(size_t)k * HD];
    g_outpart[(size_t)(b * 64 + ch) * HD + t] = acc;
}

// ---------------------------------------------------------------------------
// K4: final 64-way reduce into d_out[0 : B*HD]
// ---------------------------------------------------------------------------
__global__ void k_final(float* __restrict__ out) {
    int i = blockIdx.x * blockDim.x + threadIdx.x;   // 4096
    int b = i / HD, d = i % HD;
    float s = 0.0f;
    #pragma unroll
    for (int c = 0; c < 64; c++) s += g_outpart[(size_t)(b * 64 + c) * HD + d];
    out[i] = s;
}

// ---------------------------------------------------------------------------
extern "C" void kernel_launch(void* const* d_in, const int* in_sizes, int n_in,
                              void* d_out, int out_size) {
    const float* q    = (const float*)d_in[0];
    const float* k    = (const float*)d_in[1];
    const float* v    = (const float*)d_in[2];
    const int*   mask = (const int*)d_in[3];

    float* out = (float*)d_out;             // [0 : B*HD)             = output.sum(axis=1)
    float* p   = out + BATCH * HD;          // [B*HD : B*HD+B*SQ*SKV) = p_attn

    const size_t smem1 = (size_t)(3 * BUFB) * sizeof(__nv_bfloat16)
                       + (size_t)(QT * 4) * sizeof(float);
    cudaFuncSetAttribute(k_scores, cudaFuncAttributeMaxDynamicSharedMemorySize, (int)smem1);

    k_convert<<<BATCH * SQ * HD / 4 / 256, 256>>>(q, k);
    k_scores<<<dim3(SQ / QT, BATCH), 256, smem1>>>(mask, p);
    k_norm<<<dim3(32, BATCH), 256>>>(p);
    k_csum<<<BATCH * SKV / 256, 256>>>();
    k_gemv<<<dim3(64, BATCH), 256>>>(v);
    k_final<<<BATCH * HD / 256, 256>>>(out);
}

// round 15
// speedup vs baseline: 1.4452x; 1.4452x over previous
#include <cuda_runtime.h>
#include <cuda_bf16.h>
#include <cstdint>

#define BATCH 16
#define SQ    1024
#define SKV   1024
#define HD    256

#define QT 32              // q-rows per block
#define KT 64              // k-tile width per iteration
#define NKT (SKV / KT)     // 16
#define LDA 264            // padded bf16 leading dim (K/Q smem tiles)

// ---- static device scratch ----
__device__ __nv_bfloat16 g_qb[BATCH * SQ * HD];
__device__ __nv_bfloat16 g_kb[BATCH * SKV * HD];
__device__ float g_rowsum[BATCH * SQ];
__device__ float g_cpart[BATCH * 32 * SKV];    // per-32-row-chunk column partials
__device__ float g_outpart[BATCH * 64 * HD];   // per-kchunk GEMV partials

__device__ __forceinline__ void cp16(void* dst, const void* src) {
    unsigned int d = (unsigned int)__cvta_generic_to_shared(dst);
    asm volatile("cp.async.cg.shared.global [%0], [%1], 16;\n" :: "r"(d), "l"(src));
}

__device__ __forceinline__ void mma16816(float c[4], const unsigned a[4],
                                         unsigned b0, unsigned b1) {
    asm volatile(
        "mma.sync.aligned.m16n8k16.row.col.f32.bf16.bf16.f32 "
        "{%0,%1,%2,%3}, {%4,%5,%6,%7}, {%8,%9}, {%0,%1,%2,%3};"
        : "+f"(c[0]), "+f"(c[1]), "+f"(c[2]), "+f"(c[3])
        : "r"(a[0]), "r"(a[1]), "r"(a[2]), "r"(a[3]), "r"(b0), "r"(b1));
}

// ---------------------------------------------------------------------------
// K0: convert Q and K to bf16
// ---------------------------------------------------------------------------
__global__ void k_convert(const float* __restrict__ q, const float* __restrict__ k) {
    int i = (blockIdx.x * blockDim.x + threadIdx.x) * 4;
    float4 qv = *(const float4*)(q + i);
    float4 kv = *(const float4*)(k + i);
    __nv_bfloat162* qo = (__nv_bfloat162*)(g_qb + i);
    __nv_bfloat162* ko = (__nv_bfloat162*)(g_kb + i);
    qo[0] = __floats2bfloat162_rn(qv.x, qv.y);
    qo[1] = __floats2bfloat162_rn(qv.z, qv.w);
    ko[0] = __floats2bfloat162_rn(kv.x, kv.y);
    ko[1] = __floats2bfloat162_rn(kv.z, kv.w);
}

// ---------------------------------------------------------------------------
// K1: scores (Round-13 proven version). 32 q-rows x 1024 k per block,
//     m16n8k16 mma, 2-buffer cp.async, mask+exp in registers, direct p stores.
// ---------------------------------------------------------------------------
__global__ void __launch_bounds__(256, 2) k_scores(const int* __restrict__ mask,
                                                   float* __restrict__ p_out) {
    extern __shared__ char smraw[];
    __nv_bfloat16* Kb0 = (__nv_bfloat16*)smraw;        // 64 x LDA
    __nv_bfloat16* Kb1 = Kb0 + 64 * LDA;               // 64 x LDA (Q staging first)
    float* rowp = (float*)(Kb1 + 64 * LDA);            // 32 x 4

    const int b    = blockIdx.y;
    const int q0   = blockIdx.x * QT;
    const int tid  = threadIdx.x;
    const int lane = tid & 31;
    const int warp = tid >> 5;
    const int wy   = warp >> 2;     // 0..1 : 16-row band
    const int wx   = warp & 3;      // 0..3 : 16-col band
    const int g    = lane >> 2;     // 0..7
    const int t    = lane & 3;      // 0..3

    const __nv_bfloat16* Kg = g_kb + (size_t)b * SKV * HD;

    // stage Q -> Kb1, K tile 0 -> Kb0
    {
        const __nv_bfloat16* Qg = g_qb + (size_t)(b * SQ + q0) * HD;
        #pragma unroll
        for (int j = 0; j < 4; j++) {
            int s = tid + j * 256; int r = s >> 5, c8 = s & 31;
            cp16(Kb1 + r * LDA + c8 * 8, Qg + r * HD + c8 * 8);
        }
        #pragma unroll
        for (int j = 0; j < 8; j++) {
            int s = tid + j * 256; int r = s >> 5, c8 = s & 31;
            cp16(Kb0 + r * LDA + c8 * 8, Kg + r * HD + c8 * 8);
        }
        asm volatile("cp.async.commit_group;\n");
        asm volatile("cp.async.wait_group 0;\n");
        __syncthreads();
    }

    // hoist A fragments (all 16 dk steps) from staged Q into registers
    unsigned a[16][4];
    {
        const __nv_bfloat16* Qw = Kb1 + (wy * 16 + g) * LDA;
        #pragma unroll
        for (int dk = 0; dk < 16; dk++) {
            int base = dk * 16 + 2 * t;
            a[dk][0] = *(const unsigned*)(Qw + base);
            a[dk][1] = *(const unsigned*)(Qw + 8 * LDA + base);
            a[dk][2] = *(const unsigned*)(Qw + base + 8);
            a[dk][3] = *(const unsigned*)(Qw + 8 * LDA + base + 8);
        }
    }
    __syncthreads();   // Q reads done before prefetch overwrites Kb1

    float rs0 = 0.0f, rs1 = 0.0f;   // rowsum partials: rows wy*16+g, wy*16+g+8
    const size_t prow0 = (size_t)(b * SQ + q0 + wy * 16 + g) * SKV;

    for (int kt = 0; kt < NKT; kt++) {
        const __nv_bfloat16* cur = (kt & 1) ? Kb1 : Kb0;

        // issue prefetch of tile kt+1 (target buffer freed by prev iter's syncB)
        if (kt + 1 < NKT) {
            const __nv_bfloat16* Kn = Kg + (size_t)(kt + 1) * KT * HD;
            __nv_bfloat16* nb = ((kt + 1) & 1) ? Kb1 : Kb0;
            #pragma unroll
            for (int j = 0; j < 8; j++) {
                int s = tid + j * 256; int r = s >> 5, c8 = s & 31;
                cp16(nb + r * LDA + c8 * 8, Kn + r * HD + c8 * 8);
            }
            asm volatile("cp.async.commit_group;\n");
        }

        // mask prefetch (overlaps cp.async)
        const int* mrow = mask + prow0 + kt * KT + wx * 16 + 2 * t;
        int2 m00 = *(const int2*)(mrow);
        int2 m01 = *(const int2*)(mrow + 8);
        int2 m10 = *(const int2*)(mrow + (size_t)8 * SKV);
        int2 m11 = *(const int2*)(mrow + (size_t)8 * SKV + 8);

        if (kt + 1 < NKT) asm volatile("cp.async.wait_group 1;\n");
        else              asm volatile("cp.async.wait_group 0;\n");
        __syncthreads();   // (A) tile kt visible to all warps

        float c[2][4] = {{0.f,0.f,0.f,0.f},{0.f,0.f,0.f,0.f}};
        #pragma unroll
        for (int dk = 0; dk < 16; dk++) {
            #pragma unroll
            for (int nh = 0; nh < 2; nh++) {
                const __nv_bfloat16* Bp = cur + (wx * 16 + nh * 8 + g) * LDA + dk * 16 + 2 * t;
                unsigned b0 = *(const unsigned*)(Bp);
                unsigned b1 = *(const unsigned*)(Bp + 8);
                mma16816(c[nh], a[dk], b0, b1);
            }
        }
        __syncthreads();   // (B) smem reads of tile kt done -> buffer reusable

        // elementwise in registers + rowsum partials + direct p stores
        float* pw0 = p_out + prow0 + kt * KT + wx * 16 + 2 * t;
        #pragma unroll
        for (int nh = 0; nh < 2; nh++) {
            int2 mg  = nh ? m01 : m00;
            int2 mg8 = nh ? m11 : m10;
            float e0 = mg.x  ? __expf(__expf(c[nh][0]) * 0.0625f) : 0.0f;
            float e1 = mg.y  ? __expf(__expf(c[nh][1]) * 0.0625f) : 0.0f;
            float e2 = mg8.x ? __expf(__expf(c[nh][2]) * 0.0625f) : 0.0f;
            float e3 = mg8.y ? __expf(__expf(c[nh][3]) * 0.0625f) : 0.0f;
            rs0 += e0 + e1;
            rs1 += e2 + e3;
            *(float2*)(pw0 + nh * 8)                   = make_float2(e0, e1);
            *(float2*)(pw0 + nh * 8 + (size_t)8 * SKV) = make_float2(e2, e3);
        }
    }

    // rowsum: quad shuffle (fixed order), then 4-warp combine (fixed order)
    rs0 += __shfl_xor_sync(0xffffffffu, rs0, 1);
    rs0 += __shfl_xor_sync(0xffffffffu, rs0, 2);
    rs1 += __shfl_xor_sync(0xffffffffu, rs1, 1);
    rs1 += __shfl_xor_sync(0xffffffffu, rs1, 2);
    if (t == 0) {
        rowp[(wy * 16 + g) * 4 + wx]     = rs0;
        rowp[(wy * 16 + g + 8) * 4 + wx] = rs1;
    }
    __syncthreads();
    if (tid < QT) {
        float s = rowp[tid * 4 + 0] + rowp[tid * 4 + 1]
                + rowp[tid * 4 + 2] + rowp[tid * 4 + 3];
        g_rowsum[b * SQ + q0 + tid] = s;
    }
}

// ---------------------------------------------------------------------------
// K2: normalize p in place (float4 streaming), column partials per 32-row chunk
// ---------------------------------------------------------------------------
__global__ void __launch_bounds__(256) k_norm(float* __restrict__ p) {
    const int qc = blockIdx.x;      // 0..31 (32 rows each)
    const int b  = blockIdx.y;
    const int k4 = threadIdx.x * 4;

    __shared__ float sinv[32];
    if (threadIdx.x < 32)
        sinv[threadIdx.x] = 1.0f / g_rowsum[b * SQ + qc * 32 + threadIdx.x];
    __syncthreads();

    float* pp = p + ((size_t)b * SQ + qc * 32) * SKV + k4;
    float4 acc = {0.f, 0.f, 0.f, 0.f};
    #pragma unroll 4
    for (int q = 0; q < 32; q++) {
        float4 v = *(float4*)(pp + (size_t)q * SKV);
        float s = sinv[q];
        v.x *= s; v.y *= s; v.z *= s; v.w *= s;
        *(float4*)(pp + (size_t)q * SKV) = v;
        acc.x += v.x; acc.y += v.y; acc.z += v.z; acc.w += v.w;
    }
    *(float4*)&g_cpart[(size_t)(b * 32 + qc) * SKV + k4] = acc;
}

// ---------------------------------------------------------------------------
// K3: gemv. First parallel-reduce the 32 cpart chunks for this block's 16 k
//     (fixed-order tree -> deterministic), then pure V stream.
// ---------------------------------------------------------------------------
__global__ void __launch_bounds__(256) k_gemv(const float* __restrict__ v) {
    const int b  = blockIdx.y;
    const int ch = blockIdx.x;     // 16 k per chunk
    const int t  = threadIdx.x;

    __shared__ float red[16][17];  // [ygroup][kk], padded
    {
        int yg = t >> 4;           // 0..15
        int kk = t & 15;           // 0..15
        int k  = ch * 16 + kk;
        // fixed pairing: (2*yg) + (2*yg+1)
        float s = g_cpart[(size_t)(b * 32 + 2 * yg) * SKV + k]
                + g_cpart[(size_t)(b * 32 + 2 * yg + 1) * SKV + k];
        red[yg][kk] = s;
    }
    __syncthreads();
    #pragma unroll
    for (int st = 8; st > 0; st >>= 1) {
        int yg = t >> 4, kk = t & 15;
        if (yg < st) red[yg][kk] += red[yg + st][kk];
        __syncthreads();
    }

    const float* vb = v + ((size_t)b * SKV + ch * 16) * HD + t;
    float acc = 0.0f;
    #pragma unroll
    for (int k = 0; k < 16; k++) acc += red[0][k] * vb[(size_t)k * HD];
    g_outpart[(size_t)(b * 64 + ch) * HD + t] = acc;
}

// ---------------------------------------------------------------------------
// K4: final 64-way reduce into d_out[0 : B*HD]
// ---------------------------------------------------------------------------
__global__ void k_final(float* __restrict__ out) {
    int i = blockIdx.x * blockDim.x + threadIdx.x;   // 4096
    int b = i / HD, d = i % HD;
    float s = 0.0f;
    #pragma unroll
    for (int c = 0; c < 64; c++) s += g_outpart[(size_t)(b * 64 + c) * HD + d];
    out[i] = s;
}

// ---------------------------------------------------------------------------
extern "C" void kernel_launch(void* const* d_in, const int* in_sizes, int n_in,
                              void* d_out, int out_size) {
    const float* q    = (const float*)d_in[0];
    const float* k    = (const float*)d_in[1];
    const float* v    = (const float*)d_in[2];
    const int*   mask = (const int*)d_in[3];

    float* out = (float*)d_out;             // [0 : B*HD)             = output.sum(axis=1)
    float* p   = out + BATCH * HD;          // [B*HD : B*HD+B*SQ*SKV) = p_attn

    const size_t smem1 = (size_t)(2 * 64 * LDA) * sizeof(__nv_bfloat16)
                       + (size_t)(QT * 4) * sizeof(float);
    cudaFuncSetAttribute(k_scores, cudaFuncAttributeMaxDynamicSharedMemorySize, (int)smem1);

    k_convert<<<BATCH * SQ * HD / 4 / 256, 256>>>(q, k);
    k_scores<<<dim3(SQ / QT, BATCH), 256, smem1>>>(mask, p);
    k_norm<<<dim3(32, BATCH), 256>>>(p);
    k_gemv<<<dim3(64, BATCH), 256>>>(v);
    k_final<<<BATCH * HD / 256, 256>>>(out);
}